// round 2
// baseline (speedup 1.0000x reference)
#include <cuda_runtime.h>
#include <math.h>

#define BB 16
#define CC 128
#define HH 128
#define WW 128
#define HWSZ 16384
#define PP 256

// ---------------- scratch (static device globals; no allocation) ----------------
__device__ float g_cmax[BB*CC];        // sigmoid(max) per (b,c)
__device__ float g_xp[BB*CC*PP];       // pooled 16x16 means
__device__ float g_lapT[BB*CC*CC];     // k_c * lap, stored transposed [b][j][i]
__device__ float g_eg[BB*PP*PP];       // exp(g_s - rowmax) unnormalized
__device__ float g_rowinv[BB*PP];      // 1/rowsum for softmax
__device__ float g_enh[BB*CC*PP];      // k_s * (xp @ a_s)

// ---------------- f32x2 helpers ----------------
__device__ __forceinline__ unsigned long long pk2(float lo, float hi){
    unsigned long long r; asm("mov.b64 %0, {%1,%2};" : "=l"(r) : "f"(lo), "f"(hi)); return r;
}
__device__ __forceinline__ void upk2(unsigned long long v, float &lo, float &hi){
    asm("mov.b64 {%0,%1}, %2;" : "=f"(lo), "=f"(hi) : "l"(v));
}
__device__ __forceinline__ void fma2(unsigned long long &a, unsigned long long x, unsigned long long y){
    asm("fma.rn.f32x2 %0, %1, %2, %0;" : "+l"(a) : "l"(x), "l"(y));
}

// ---------------- kernel 1: per-(b,c) max + 16x16 pooled means ----------------
__global__ void __launch_bounds__(256) k_reduce(const float* __restrict__ x){
    int bc = blockIdx.x;                       // 0..2047
    int t  = threadIdx.x;                      // 256: one pooled cell each
    int ph = t >> 4, pw = t & 15;
    const float4* q4 = (const float4*)(x + (size_t)bc*HWSZ + ph*8*WW + pw*8);
    float s = 0.f, m = -1e30f;
    #pragma unroll
    for (int r = 0; r < 8; r++){
        float4 a = __ldg(q4 + r*32);
        float4 b = __ldg(q4 + r*32 + 1);
        s += (a.x+a.y)+(a.z+a.w) + (b.x+b.y)+(b.z+b.w);
        m = fmaxf(m, fmaxf(fmaxf(a.x,a.y), fmaxf(a.z,a.w)));
        m = fmaxf(m, fmaxf(fmaxf(b.x,b.y), fmaxf(b.z,b.w)));
    }
    g_xp[bc*PP + t] = s * (1.f/64.f);
    __shared__ float red[256];
    red[t] = m; __syncthreads();
    for (int o = 128; o > 0; o >>= 1){ if (t < o) red[t] = fmaxf(red[t], red[t+o]); __syncthreads(); }
    if (t == 0) g_cmax[bc] = 1.f / (1.f + __expf(-red[0]));
}

// ---------------- block reduce helpers (256 threads) ----------------
__device__ __forceinline__ float blkSum(float v, float* red){
    int t = threadIdx.x; red[t] = v; __syncthreads();
    for (int o = 128; o > 0; o >>= 1){ if (t < o) red[t] += red[t+o]; __syncthreads(); }
    float r = red[0]; __syncthreads(); return r;
}
__device__ __forceinline__ float blkMax(float v, float* red){
    int t = threadIdx.x; red[t] = v; __syncthreads();
    for (int o = 128; o > 0; o >>= 1){ if (t < o) red[t] = fmaxf(red[t], red[t+o]); __syncthreads(); }
    float r = red[0]; __syncthreads(); return r;
}
__device__ __forceinline__ float blkMin(float v, float* red){
    int t = threadIdx.x; red[t] = v; __syncthreads();
    for (int o = 128; o > 0; o >>= 1){ if (t < o) red[t] = fminf(red[t], red[t+o]); __syncthreads(); }
    float r = red[0]; __syncthreads(); return r;
}

// ---------------- kernel 2a: per-batch lap + spatial softmax stats ----------------
__global__ void __launch_bounds__(256) k_small(){
    __shared__ float red[256];
    __shared__ float cm[CC], rn[CC], inv2s[CC], rowS[CC], colS[CC];
    __shared__ float v[PP], invq[PP];
    int b = blockIdx.x, t = threadIdx.x;

    // ---- channel residual matrix ----
    if (t < CC) cm[t] = g_cmax[b*CC + t];
    __syncthreads();
    float cmv = (t < CC) ? cm[t] : 0.f;
    float S1 = blkSum(cmv, red);
    float S2 = blkSum(cmv*cmv, red);
    float nloc = -1e30f;
    if (t < CC){
        float tt = 1.f - cmv;
        float n2 = S2 + 2.f*tt*S1 + 128.f*tt*tt;     // sum_i (cm_i + (1-cm_j))^2
        float n  = sqrtf(n2);
        nloc = n;
        rn[t] = 1.f / fmaxf(n, 1e-12f);
    }
    float nmax = blkMax(nloc, red);
    float r = fminf(1.f / fmaxf(nmax, 1e-12f), 1.f);  // min over diag(1/norm), cap at 1
    if (t < CC){
        float mn = 1e30f;
        for (int j = 0; j < CC; j++) mn = fminf(mn, (cmv + (1.f - cm[j])) * rn[j]);
        float sg = fmaxf(mn, 0.5f);
        inv2s[t] = 1.f / (2.f*sg*sg + 1e-8f);
    }
    __syncthreads();
    if (t < CC){
        float is = inv2s[t], s = 0.f;
        for (int j = 0; j < CC; j++){
            float d = fabsf(cmv - cm[j]) - r;
            float g = __expf(-d*d*is);
            s += g*g;
        }
        rowS[t] = s;
        float s2 = 0.f;
        for (int i = 0; i < CC; i++){
            float d = fabsf(cm[i] - cmv) - r;
            float g = __expf(-d*d*inv2s[i]);
            s2 += g*g;
        }
        colS[t] = s2;
    }
    __syncthreads();
    const float kc = (float)(128.0/384.0);
    float* lapB = g_lapT + (size_t)b*CC*CC;
    for (int idx = t; idx < CC*CC; idx += 256){
        int i = idx & 127, j = idx >> 7;              // lapT[j][i]
        float a = 0.5f*(sqrtf(rowS[i]+colS[j]) + sqrtf(rowS[j]+colS[i]));
        lapB[idx] = kc * cm[i] * ((i==j ? 1.f : 0.f) + a);
    }

    // ---- spatial attention stats ----
    float vv = 0.f;
    for (int c = 0; c < CC; c++) vv += g_xp[((size_t)b*CC + c)*PP + t];
    vv *= (1.f/128.f);
    v[t] = vv;
    __syncthreads();
    float vn2 = blkSum(vv*vv, red);
    float nv = sqrtf(vn2);
    float ns = fabsf(vv)*nv;
    float rns = 1.f / fmaxf(ns, 1e-12f);
    float diag = vv*vv*rns;
    float rs = fminf(blkMin(diag, red), 1.f);
    {
        float mn = 1e30f;
        for (int q = 0; q < PP; q++) mn = fminf(mn, vv*v[q]);
        float sg = fmaxf(mn*rns, 0.5f);
        invq[t] = 1.f / (2.f*sg*sg + 1e-8f);
    }
    __syncthreads();
    // softmax over q, unnormalized exp written out; 1/sum stored
    float M = -1e30f;
    for (int q = 0; q < PP; q++){
        float d = fabsf(vv - v[q]) - rs;
        float g = __expf(-d*d*invq[q]);
        M = fmaxf(M, g);
    }
    float ssum = 0.f;
    float* outp = g_eg + ((size_t)b*PP + t)*PP;
    for (int q = 0; q < PP; q++){
        float d = fabsf(vv - v[q]) - rs;
        float g = __expf(-d*d*invq[q]);
        float e = __expf(g - M);
        ssum += e;
        outp[q] = e;
    }
    g_rowinv[b*PP + t] = 1.f/ssum;
}

// ---------------- kernel 2b: enh = k_s * (xp*rowinv) @ eg ----------------
__global__ void __launch_bounds__(256) k_enh(){
    int b = blockIdx.y;
    int t = threadIdx.x;
    int c = blockIdx.x*16 + (t >> 4);
    int q0 = (t & 15) * 16;
    const float* xpr = g_xp + ((size_t)b*CC + c)*PP;
    const float* ri  = g_rowinv + b*PP;
    float acc[16];
    #pragma unroll
    for (int k = 0; k < 16; k++) acc[k] = 0.f;
    const float* egB = g_eg + (size_t)b*PP*PP;
    #pragma unroll 4
    for (int p = 0; p < PP; p++){
        float xv = __ldg(xpr + p) * __ldg(ri + p);
        const float4* a4 = (const float4*)(egB + (size_t)p*PP + q0);
        float4 A = __ldg(a4), Bv = __ldg(a4+1), Cv = __ldg(a4+2), D = __ldg(a4+3);
        acc[0]+=xv*A.x;  acc[1]+=xv*A.y;  acc[2]+=xv*A.z;  acc[3]+=xv*A.w;
        acc[4]+=xv*Bv.x; acc[5]+=xv*Bv.y; acc[6]+=xv*Bv.z; acc[7]+=xv*Bv.w;
        acc[8]+=xv*Cv.x; acc[9]+=xv*Cv.y; acc[10]+=xv*Cv.z; acc[11]+=xv*Cv.w;
        acc[12]+=xv*D.x; acc[13]+=xv*D.y; acc[14]+=xv*D.z; acc[15]+=xv*D.w;
    }
    const float ks = (float)(256.0/384.0);
    float* o = g_enh + ((size_t)b*CC + c)*PP + q0;
    #pragma unroll
    for (int k = 0; k < 16; k += 4){
        float4 w = make_float4(acc[k]*ks, acc[k+1]*ks, acc[k+2]*ks, acc[k+3]*ks);
        *(float4*)(o + k) = w;
    }
}

// ---------------- kernel 3: out = x + lap@x + bilinear(enh) ----------------
// grid: (2 w-tiles, 128 h, 16 b), 256 threads, dyn smem 112KB (2 CTA/SM)
__global__ void __launch_bounds__(256) k_main(const float* __restrict__ x, float* __restrict__ out){
    extern __shared__ float sm[];
    float* sLap = sm;               // [128][128]
    float* sX   = sm + 16384;       // [128][64]
    float* sE   = sm + 16384+8192;  // [2][128][16]
    int b = blockIdx.z, h = blockIdx.y, w0 = blockIdx.x*64;
    int t = threadIdx.x;

    // load lapT (64KB)
    {
        const float4* lg = (const float4*)(g_lapT + (size_t)b*CC*CC);
        float4* ls = (float4*)sLap;
        #pragma unroll
        for (int i = 0; i < 16; i++) ls[i*256 + t] = __ldg(lg + i*256 + t);
    }
    // load X tile: 128 channels x 64 w
    {
        const float* xb = x + (size_t)b*CC*HWSZ + h*WW + w0;
        float4* sX4 = (float4*)sX;
        #pragma unroll
        for (int it = 0; it < 8; it++){
            int lin = it*256 + t;
            int j = lin >> 4, f = lin & 15;
            sX4[lin] = __ldg((const float4*)(xb + (size_t)j*HWSZ) + f);
        }
    }
    // vertical bilinear coords for this h
    float sy = h*0.125f - 0.4375f;
    float fl = floorf(sy);
    float fy = sy - fl;
    int iy0 = (int)fl;
    int iy0c = iy0 < 0 ? 0 : iy0;
    int iy1c = (iy0+1) > 15 ? 15 : (iy0+1);
    // load 2 enh rows for all channels
    {
        const float* eb = g_enh + (size_t)b*CC*PP;
        #pragma unroll
        for (int it = 0; it < 16; it++){
            int idx = it*256 + t;
            int py = idx >> 11, c = (idx >> 4) & 127, px = idx & 15;
            int iy = py ? iy1c : iy0c;
            sE[idx] = eb[c*PP + iy*16 + px];
        }
    }
    __syncthreads();

    int nb = t & 15, ib = t >> 4;
    int n0 = nb*4;
    unsigned long long acc[4][4];
    #pragma unroll
    for (int ip = 0; ip < 4; ip++)
        #pragma unroll
        for (int k = 0; k < 4; k++) acc[ip][k] = 0ull;

    const float4* sX4 = (const float4*)sX;
    #pragma unroll 8
    for (int j = 0; j < 128; j++){
        float4 xv = sX4[j*16 + nb];
        unsigned long long x0 = pk2(xv.x, xv.x);
        unsigned long long x1 = pk2(xv.y, xv.y);
        unsigned long long x2 = pk2(xv.z, xv.z);
        unsigned long long x3 = pk2(xv.w, xv.w);
        const ulonglong2* lp = (const ulonglong2*)(sLap + j*128 + ib*8);
        ulonglong2 A = lp[0], Bv = lp[1];
        fma2(acc[0][0], A.x, x0); fma2(acc[0][1], A.x, x1); fma2(acc[0][2], A.x, x2); fma2(acc[0][3], A.x, x3);
        fma2(acc[1][0], A.y, x0); fma2(acc[1][1], A.y, x1); fma2(acc[1][2], A.y, x2); fma2(acc[1][3], A.y, x3);
        fma2(acc[2][0], Bv.x, x0); fma2(acc[2][1], Bv.x, x1); fma2(acc[2][2], Bv.x, x2); fma2(acc[2][3], Bv.x, x3);
        fma2(acc[3][0], Bv.y, x0); fma2(acc[3][1], Bv.y, x1); fma2(acc[3][2], Bv.y, x2); fma2(acc[3][3], Bv.y, x3);
    }

    // epilogue: + x + bilinear(enh)
    float fxk[4]; int ix0c[4], ix1c[4];
    #pragma unroll
    for (int k = 0; k < 4; k++){
        int w = w0 + n0 + k;
        float sx = w*0.125f - 0.4375f;
        float f2 = floorf(sx);
        fxk[k] = sx - f2;
        int i0 = (int)f2;
        ix0c[k] = i0 < 0 ? 0 : i0;
        ix1c[k] = (i0+1) > 15 ? 15 : (i0+1);
    }
    float* outB = out + (size_t)b*CC*HWSZ + h*WW + w0 + n0;
    int iBase = ib*8;
    #pragma unroll
    for (int ip = 0; ip < 4; ip++){
        int i0 = iBase + 2*ip;
        float o0[4], o1[4];
        const float* E0a = sE + i0*16;           // row iy0, channel i0
        const float* E1a = sE + 2048 + i0*16;    // row iy1, channel i0
        const float* E0b = E0a + 16;             // channel i0+1
        const float* E1b = E1a + 16;
        #pragma unroll
        for (int k = 0; k < 4; k++){
            float lo, hi; upk2(acc[ip][k], lo, hi);
            float fx = fxk[k];
            // channel i0
            float e00 = E0a[ix0c[k]], e01 = E0a[ix1c[k]];
            float e10 = E1a[ix0c[k]], e11 = E1a[ix1c[k]];
            float b0 = e00 + fx*(e01-e00);
            float b1 = e10 + fx*(e11-e10);
            float bil = b0 + fy*(b1-b0);
            o0[k] = sX[i0*64 + n0 + k] + lo + bil;
            // channel i0+1
            float f00 = E0b[ix0c[k]], f01 = E0b[ix1c[k]];
            float f10 = E1b[ix0c[k]], f11 = E1b[ix1c[k]];
            float c0 = f00 + fx*(f01-f00);
            float c1 = f10 + fx*(f11-f10);
            float bil2 = c0 + fy*(c1-c0);
            o1[k] = sX[(i0+1)*64 + n0 + k] + hi + bil2;
        }
        *(float4*)(outB + (size_t)i0*HWSZ)     = make_float4(o0[0], o0[1], o0[2], o0[3]);
        *(float4*)(outB + (size_t)(i0+1)*HWSZ) = make_float4(o1[0], o1[1], o1[2], o1[3]);
    }
}

extern "C" void kernel_launch(void* const* d_in, const int* in_sizes, int n_in,
                              void* d_out, int out_size){
    const float* x = (const float*)d_in[0];
    float* out = (float*)d_out;
    (void)in_sizes; (void)n_in; (void)out_size;

    k_reduce<<<BB*CC, 256>>>(x);
    k_small<<<BB, 256>>>();
    k_enh<<<dim3(8, BB), 256>>>();
    cudaFuncSetAttribute(k_main, cudaFuncAttributeMaxDynamicSharedMemorySize, 114688);
    k_main<<<dim3(2, HH, BB), 256, 114688>>>(x, out);
}

// round 5
// speedup vs baseline: 1.0767x; 1.0767x over previous
#include <cuda_runtime.h>
#include <cuda_bf16.h>
#include <math.h>
#include <stdint.h>

#define BB 16
#define CC 128
#define HH 128
#define HWSZ 16384
#define PP 256
#define ASTRIDE 136            // bf16 elems per row (padded)
#define ABYTES 34816           // 128*136*2

// ---------------- scratch ----------------
__device__ float g_cmax[BB*CC];
__device__ float g_xp[BB*CC*PP];
__device__ __align__(16) unsigned char g_Ahi[BB*ABYTES]; // I + kc*lap, bf16 hi, row-major stride 136
__device__ __align__(16) unsigned char g_Alo[BB*ABYTES]; // bf16 lo residual
__device__ float g_v[BB*PP];
__device__ float g_invq[BB*PP];
__device__ float g_Mrow[BB*PP];
__device__ float g_rs[BB];
__device__ float g_eg[BB*PP*PP];
__device__ float g_rowinv[BB*PP];
__device__ float g_enh[BB*CC*PP];   // k_s * (xp @ a_s)

__device__ __forceinline__ uint32_t smem_u32(const void* p){
    uint32_t a;
    asm("{ .reg .u64 tmp; cvta.to.shared.u64 tmp, %1; cvt.u32.u64 %0, tmp; }" : "=r"(a) : "l"(p));
    return a;
}
#define LDSM4(r, addr) \
    asm volatile("ldmatrix.sync.aligned.m8n8.x4.shared.b16 {%0,%1,%2,%3}, [%4];" \
        : "=r"((r)[0]),"=r"((r)[1]),"=r"((r)[2]),"=r"((r)[3]) : "r"(addr))
#define MMA(d, a, b0, b1) \
    asm volatile("mma.sync.aligned.m16n8k16.row.col.f32.bf16.bf16.f32 " \
        "{%0,%1,%2,%3}, {%4,%5,%6,%7}, {%8,%9}, {%0,%1,%2,%3};" \
        : "+f"((d)[0]),"+f"((d)[1]),"+f"((d)[2]),"+f"((d)[3]) \
        : "r"((a)[0]),"r"((a)[1]),"r"((a)[2]),"r"((a)[3]), "r"(b0),"r"(b1))

// ---------------- kernel 1: per-(b,c) max + pooled means ----------------
__global__ void __launch_bounds__(256) k_reduce(const float* __restrict__ x){
    int bc = blockIdx.x, t = threadIdx.x;
    int ph = t >> 4, pw = t & 15;
    const float4* q4 = (const float4*)(x + (size_t)bc*HWSZ + ph*8*128 + pw*8);
    float s = 0.f, m = -1e30f;
    #pragma unroll
    for (int r = 0; r < 8; r++){
        float4 a = __ldg(q4 + r*32);
        float4 b = __ldg(q4 + r*32 + 1);
        s += (a.x+a.y)+(a.z+a.w) + (b.x+b.y)+(b.z+b.w);
        m = fmaxf(m, fmaxf(fmaxf(a.x,a.y), fmaxf(a.z,a.w)));
        m = fmaxf(m, fmaxf(fmaxf(b.x,b.y), fmaxf(b.z,b.w)));
    }
    g_xp[bc*PP + t] = s * (1.f/64.f);
    __shared__ float red[256];
    red[t] = m; __syncthreads();
    for (int o = 128; o > 0; o >>= 1){ if (t < o) red[t] = fmaxf(red[t], red[t+o]); __syncthreads(); }
    if (t == 0) g_cmax[bc] = 1.f / (1.f + __expf(-red[0]));
}

__device__ __forceinline__ float blkSum(float v, float* red){
    int t = threadIdx.x; red[t] = v; __syncthreads();
    for (int o = 128; o > 0; o >>= 1){ if (t < o) red[t] += red[t+o]; __syncthreads(); }
    float r = red[0]; __syncthreads(); return r;
}
__device__ __forceinline__ float blkMax(float v, float* red){
    int t = threadIdx.x; red[t] = v; __syncthreads();
    for (int o = 128; o > 0; o >>= 1){ if (t < o) red[t] = fmaxf(red[t], red[t+o]); __syncthreads(); }
    float r = red[0]; __syncthreads(); return r;
}
__device__ __forceinline__ float blkMin(float v, float* red){
    int t = threadIdx.x; red[t] = v; __syncthreads();
    for (int o = 128; o > 0; o >>= 1){ if (t < o) red[t] = fminf(red[t], red[t+o]); __syncthreads(); }
    float r = red[0]; __syncthreads(); return r;
}

// ---------------- kernel 2a: A = I + kc*lap (bf16 split) + spatial row stats ----------------
__global__ void __launch_bounds__(256) k_small(){
    __shared__ float red[256];
    __shared__ float cm[CC], rn[CC], inv2s[CC], rowS[CC], colS[CC];
    __shared__ float v[PP], invq[PP];
    int b = blockIdx.x, t = threadIdx.x;

    if (t < CC) cm[t] = g_cmax[b*CC + t];
    __syncthreads();
    float cmv = (t < CC) ? cm[t] : 0.f;
    float S1 = blkSum(cmv, red);
    float S2 = blkSum(cmv*cmv, red);
    float nloc = -1e30f;
    if (t < CC){
        float tt = 1.f - cmv;
        float n2 = S2 + 2.f*tt*S1 + 128.f*tt*tt;
        float n  = sqrtf(n2);
        nloc = n;
        rn[t] = 1.f / fmaxf(n, 1e-12f);
    }
    float nmax = blkMax(nloc, red);
    float r = fminf(1.f / fmaxf(nmax, 1e-12f), 1.f);
    if (t < CC){
        float mn = 1e30f;
        for (int j = 0; j < CC; j++) mn = fminf(mn, (cmv + (1.f - cm[j])) * rn[j]);
        float sg = fmaxf(mn, 0.5f);
        inv2s[t] = 1.f / (2.f*sg*sg + 1e-8f);
    }
    __syncthreads();
    if (t < CC){
        float is = inv2s[t], s = 0.f, s2 = 0.f;
        for (int j = 0; j < CC; j++){
            float d = fabsf(cmv - cm[j]) - r;
            float g = __expf(-d*d*is);
            s += g*g;
            float g2 = __expf(-d*d*inv2s[j]);
            s2 += g2*g2;
        }
        rowS[t] = s;
        colS[t] = s2;
    }
    __syncthreads();
    const float kc = (float)(128.0/384.0);
    unsigned char* Ah = g_Ahi + (size_t)b*ABYTES;
    unsigned char* Al = g_Alo + (size_t)b*ABYTES;
    for (int idx = t; idx < CC*CC; idx += 256){
        int i = idx >> 7, k = idx & 127;
        float a = 0.5f*(sqrtf(rowS[i]+colS[k]) + sqrtf(rowS[k]+colS[i]));
        float dlt = (i == k) ? 1.f : 0.f;
        float val = kc * cm[i] * (dlt + a) + dlt;           // A = I + kc*lap
        __nv_bfloat16 hi = __float2bfloat16(val);
        __nv_bfloat16 lo = __float2bfloat16(val - __bfloat162float(hi));
        uint32_t o = (uint32_t)(i*ASTRIDE + k)*2u;
        *(__nv_bfloat16*)(Ah + o) = hi;
        *(__nv_bfloat16*)(Al + o) = lo;
    }

    // ---- spatial row stats ----
    float vv = 0.f;
    for (int c = 0; c < CC; c++) vv += g_xp[((size_t)b*CC + c)*PP + t];
    vv *= (1.f/128.f);
    v[t] = vv;
    __syncthreads();
    float vn2 = blkSum(vv*vv, red);
    float nv = sqrtf(vn2);
    float ns = fabsf(vv)*nv;
    float rns = 1.f / fmaxf(ns, 1e-12f);
    float diag = vv*vv*rns;
    float rs = fminf(blkMin(diag, red), 1.f);
    {
        float mn = 1e30f;
        for (int q = 0; q < PP; q++) mn = fminf(mn, vv*v[q]);
        float sg = fmaxf(mn*rns, 0.5f);
        invq[t] = 1.f/(2.f*sg*sg + 1e-8f);
    }
    __syncthreads();
    float M = -1e30f;
    for (int q = 0; q < PP; q++){
        float d = fabsf(vv - v[q]) - rs;
        float g = __expf(-d*d*invq[q]);
        M = fmaxf(M, g);
    }
    float ssum = 0.f;
    for (int q = 0; q < PP; q++){
        float d = fabsf(vv - v[q]) - rs;
        float g = __expf(-d*d*invq[q]);
        ssum += __expf(g - M);
    }
    g_v[b*PP+t] = vv;
    g_invq[b*PP+t] = invq[t];
    g_Mrow[b*PP+t] = M;
    g_rowinv[b*PP+t] = 1.f/ssum;
    if (t == 0) g_rs[b] = rs;
}

// ---------------- kernel 2b: eg written coalesced ----------------
__global__ void __launch_bounds__(256) k_eg(){
    __shared__ float sv[PP], siq[PP];
    int b = blockIdx.x >> 4, pg = blockIdx.x & 15, t = threadIdx.x;
    sv[t] = g_v[b*PP + t];
    siq[t] = g_invq[b*PP + t];
    __syncthreads();
    float rs = g_rs[b];
    float iqt = siq[t];
    #pragma unroll 4
    for (int rr = 0; rr < 16; rr++){
        int p = pg*16 + rr;
        float vp = sv[p];
        float M = __ldg(g_Mrow + b*PP + p);
        float d = fabsf(vp - sv[t]) - rs;
        float g = __expf(-d*d*iqt);
        g_eg[((size_t)b*PP + p)*PP + t] = __expf(g - M);
    }
}

// ---------------- kernel 2c: enh = k_s * (xp*rowinv) @ eg ----------------
__global__ void __launch_bounds__(256) k_enh(){
    int b = blockIdx.y, t = threadIdx.x;
    int c = blockIdx.x*16 + (t >> 4);
    int q0 = (t & 15) * 16;
    const float* xpr = g_xp + ((size_t)b*CC + c)*PP;
    const float* ri  = g_rowinv + b*PP;
    float acc[16];
    #pragma unroll
    for (int k = 0; k < 16; k++) acc[k] = 0.f;
    const float* egB = g_eg + (size_t)b*PP*PP;
    #pragma unroll 4
    for (int p = 0; p < PP; p++){
        float xv = __ldg(xpr + p) * __ldg(ri + p);
        const float4* a4 = (const float4*)(egB + (size_t)p*PP + q0);
        float4 A = __ldg(a4), Bv = __ldg(a4+1), Cv = __ldg(a4+2), D = __ldg(a4+3);
        acc[0]+=xv*A.x;  acc[1]+=xv*A.y;  acc[2]+=xv*A.z;  acc[3]+=xv*A.w;
        acc[4]+=xv*Bv.x; acc[5]+=xv*Bv.y; acc[6]+=xv*Bv.z; acc[7]+=xv*Bv.w;
        acc[8]+=xv*Cv.x; acc[9]+=xv*Cv.y; acc[10]+=xv*Cv.z; acc[11]+=xv*Cv.w;
        acc[12]+=xv*D.x; acc[13]+=xv*D.y; acc[14]+=xv*D.z; acc[15]+=xv*D.w;
    }
    const float ks = (float)(256.0/384.0);
    float* o = g_enh + ((size_t)b*CC + c)*PP + q0;
    #pragma unroll
    for (int k = 0; k < 16; k += 4)
        *(float4*)(o + k) = make_float4(acc[k]*ks, acc[k+1]*ks, acc[k+2]*ks, acc[k+3]*ks);
}

// ---------------- kernel 3: mma.sync GEMM + bilinear epilogue ----------------
// smem byte offsets (16B aligned)
#define SM_AH  0
#define SM_AL  34816
#define SM_BH  69632
#define SM_BL  104448
#define SM_STG 139264   // 32*129 fp32 = 16512 -> pad 16640
#define SM_EY  155904   // 128*17 fp32 = 8704
#define SM_WX  164608   // 128 fp32
#define SM_IX  165120   // 128 int
#define SM_TOTAL 165632

__global__ void __launch_bounds__(256) k_main(const float* __restrict__ x, float* __restrict__ out){
    extern __shared__ __align__(16) unsigned char sm[];
    uint32_t sb = smem_u32(sm);
    int t = threadIdx.x, wid = t >> 5, lane = t & 31;
    int h = blockIdx.x, b = blockIdx.y;

    // copy A hi/lo (2 x 34816 B) via float4
    {
        const float4* ag  = (const float4*)(g_Ahi + (size_t)b*ABYTES);
        const float4* alg = (const float4*)(g_Alo + (size_t)b*ABYTES);
        float4* sa  = (float4*)(sm + SM_AH);
        float4* sal = (float4*)(sm + SM_AL);
        for (int i = t; i < ABYTES/16; i += 256){
            sa[i]  = __ldg(ag + i);
            sal[i] = __ldg(alg + i);
        }
    }
    // bilinear precompute
    float sy = h*0.125f - 0.4375f;
    float fl = floorf(sy);
    float fy = sy - fl;
    int iy0 = (int)fl;
    int iy0c = iy0 < 0 ? 0 : iy0;
    int iy1c = iy0+1 > 15 ? 15 : iy0+1;
    if (t < 128){
        float sx = t*0.125f - 0.4375f;
        float f2 = floorf(sx);
        int i0 = (int)f2;
        int i0c = i0 < 0 ? 0 : i0;
        int i1c = i0+1 > 15 ? 15 : i0+1;
        ((float*)(sm + SM_WX))[t] = sx - f2;
        ((int*)(sm + SM_IX))[t] = i0c | (i1c << 8);
        const float* eb = g_enh + ((size_t)b*CC + t)*PP;
        float* ey = (float*)(sm + SM_EY) + t*17;
        #pragma unroll
        for (int px = 0; px < 16; px++){
            float e0 = __ldg(eb + iy0c*16 + px);
            float e1 = __ldg(eb + iy1c*16 + px);
            ey[px] = e0 + fy*(e1 - e0);
        }
    }

    // transpose x -> xT[n=w][k=c] bf16 hi/lo, 4 chunks of 32 channels via fp32 staging
    {
        float* stg = (float*)(sm + SM_STG);           // [32][129]
        const float* xb = x + (size_t)b*CC*HWSZ + h*128;
        for (int chunk = 0; chunk < 4; chunk++){
            __syncthreads();
            #pragma unroll
            for (int i = 0; i < 4; i++){
                int lin = i*256 + t;                   // float4 units, 1024 total
                int c = lin >> 5, wf = lin & 31;
                float4 vv = __ldg((const float4*)(xb + (size_t)(chunk*32 + c)*HWSZ) + wf);
                float* d = stg + c*129 + wf*4;
                d[0] = vv.x; d[1] = vv.y; d[2] = vv.z; d[3] = vv.w;
            }
            __syncthreads();
            int w = t & 127, half = t >> 7;            // half: 16 channels each
            int c0 = half*16;
            uint32_t hi[8], lo[8];
            #pragma unroll
            for (int p = 0; p < 8; p++){
                float f0 = stg[(c0 + 2*p)*129 + w];
                float f1 = stg[(c0 + 2*p + 1)*129 + w];
                uint32_t hp;
                asm("cvt.rn.bf16x2.f32 %0, %1, %2;" : "=r"(hp) : "f"(f1), "f"(f0));
                hi[p] = hp;
                float h0 = __uint_as_float(hp << 16);
                float h1 = __uint_as_float(hp & 0xFFFF0000u);
                uint32_t lp;
                float l0 = f0 - h0, l1 = f1 - h1;
                asm("cvt.rn.bf16x2.f32 %0, %1, %2;" : "=r"(lp) : "f"(l1), "f"(l0));
                lo[p] = lp;
            }
            uint32_t o = (uint32_t)(w*ASTRIDE + chunk*32 + c0)*2u;
            *(uint4*)(sm + SM_BH + o)      = make_uint4(hi[0],hi[1],hi[2],hi[3]);
            *(uint4*)(sm + SM_BH + o + 16) = make_uint4(hi[4],hi[5],hi[6],hi[7]);
            *(uint4*)(sm + SM_BL + o)      = make_uint4(lo[0],lo[1],lo[2],lo[3]);
            *(uint4*)(sm + SM_BL + o + 16) = make_uint4(lo[4],lo[5],lo[6],lo[7]);
        }
    }
    __syncthreads();

    // ---- mainloop: warp wid computes rows [wid*16, wid*16+16) x 128 cols ----
    int m0 = wid*16;
    int lr = lane & 7;
    uint32_t aA = sb + SM_AH + (uint32_t)(((m0 + lr + (lane & 8))*ASTRIDE + ((lane>>4)<<3))*2);
    uint32_t nB = (uint32_t)(lr + (((lane>>4)&1)<<3));
    uint32_t kB = (uint32_t)(((lane>>3)&1)<<3);
    uint32_t aB = sb + SM_BH + (nB*ASTRIDE + kB)*2u;

    float acc[64];
    #pragma unroll
    for (int i = 0; i < 64; i++) acc[i] = 0.f;

    #pragma unroll
    for (int ks = 0; ks < 8; ks++){
        uint32_t kOff = (uint32_t)(ks*32);             // k0*2 bytes
        uint32_t ah[4], al[4];
        LDSM4(ah, aA + kOff);
        LDSM4(al, aA + (SM_AL - SM_AH) + kOff);
        #pragma unroll
        for (int np = 0; np < 8; np++){
            uint32_t bOff = (uint32_t)(np*16*ASTRIDE*2) + kOff;
            uint32_t bh[4], bl[4];
            LDSM4(bh, aB + bOff);
            LDSM4(bl, aB + (SM_BL - SM_BH) + bOff);
            float* d0 = acc + np*8;
            float* d1 = acc + np*8 + 4;
            MMA(d0, ah, bh[0], bh[1]);
            MMA(d1, ah, bh[2], bh[3]);
            MMA(d0, ah, bl[0], bl[1]);
            MMA(d1, ah, bl[2], bl[3]);
            MMA(d0, al, bh[0], bh[1]);
            MMA(d1, al, bh[2], bh[3]);
        }
    }

    // ---- epilogue: + bilinear, direct stores ----
    {
        int g = lane >> 2, tig = lane & 3;
        int r0 = m0 + g, r1 = r0 + 8;
        const float* ey0 = (const float*)(sm + SM_EY) + r0*17;
        const float* ey1 = (const float*)(sm + SM_EY) + r1*17;
        const float* swx = (const float*)(sm + SM_WX);
        const int*   six = (const int*)(sm + SM_IX);
        float* outB = out + (size_t)b*CC*HWSZ + h*128;
        #pragma unroll
        for (int nt = 0; nt < 16; nt++){
            int n = nt*8 + tig*2;
            const float* d = acc + (nt>>1)*8 + (nt&1)*4;
            int pa = six[n], pb = six[n+1];
            float wa = swx[n], wb = swx[n+1];
            int pa0 = pa & 255, pa1 = (pa >> 8) & 255;
            int pb0 = pb & 255, pb1 = (pb >> 8) & 255;
            float ea = ey0[pa0] + wa*(ey0[pa1] - ey0[pa0]);
            float eb = ey0[pb0] + wb*(ey0[pb1] - ey0[pb0]);
            *(float2*)(outB + (size_t)r0*HWSZ + n) = make_float2(d[0] + ea, d[1] + eb);
            float fa = ey1[pa0] + wa*(ey1[pa1] - ey1[pa0]);
            float fb = ey1[pb0] + wb*(ey1[pb1] - ey1[pb0]);
            *(float2*)(outB + (size_t)r1*HWSZ + n) = make_float2(d[2] + fa, d[3] + fb);
        }
    }
}

extern "C" void kernel_launch(void* const* d_in, const int* in_sizes, int n_in,
                              void* d_out, int out_size){
    const float* x = (const float*)d_in[0];
    float* out = (float*)d_out;
    (void)in_sizes; (void)n_in; (void)out_size;

    k_reduce<<<BB*CC, 256>>>(x);
    k_small<<<BB, 256>>>();
    k_eg<<<BB*16, 256>>>();
    k_enh<<<dim3(8, BB), 256>>>();
    cudaFuncSetAttribute(k_main, cudaFuncAttributeMaxDynamicSharedMemorySize, SM_TOTAL);
    k_main<<<dim3(HH, BB), 256, SM_TOTAL>>>(x, out);
}

// round 6
// speedup vs baseline: 1.3332x; 1.2382x over previous
#include <cuda_runtime.h>
#include <cuda_bf16.h>
#include <math.h>
#include <stdint.h>

#define BB 16
#define CC 128
#define HH 128
#define HWSZ 16384
#define PP 256
#define ASTRIDE 136            // bf16 elems per row (padded)
#define ABYTES 34816           // 128*136*2

// ---------------- scratch ----------------
__device__ float g_cmax[BB*CC];
__device__ float g_xp[BB*CC*PP];
__device__ __align__(16) unsigned char g_Ahi[BB*ABYTES]; // I + kc*lap, bf16 hi
__device__ __align__(16) unsigned char g_Alo[BB*ABYTES]; // bf16 lo residual
__device__ float g_v[BB*PP];
__device__ float g_invq[BB*PP];
__device__ float g_rs[BB];
__device__ float g_eg[BB*PP*PP];
__device__ float g_rowinv[BB*PP];
__device__ float g_enh[BB*CC*PP];   // k_s * (xp @ a_s)

__device__ __forceinline__ uint32_t smem_u32(const void* p){
    uint32_t a;
    asm("{ .reg .u64 tmp; cvta.to.shared.u64 tmp, %1; cvt.u32.u64 %0, tmp; }" : "=r"(a) : "l"(p));
    return a;
}
#define LDSM4(r, addr) \
    asm volatile("ldmatrix.sync.aligned.m8n8.x4.shared.b16 {%0,%1,%2,%3}, [%4];" \
        : "=r"((r)[0]),"=r"((r)[1]),"=r"((r)[2]),"=r"((r)[3]) : "r"(addr))
#define MMA(d, a, b0, b1) \
    asm volatile("mma.sync.aligned.m16n8k16.row.col.f32.bf16.bf16.f32 " \
        "{%0,%1,%2,%3}, {%4,%5,%6,%7}, {%8,%9}, {%0,%1,%2,%3};" \
        : "+f"((d)[0]),"+f"((d)[1]),"+f"((d)[2]),"+f"((d)[3]) \
        : "r"((a)[0]),"r"((a)[1]),"r"((a)[2]),"r"((a)[3]), "r"(b0),"r"(b1))

// ---------------- kernel 1: per-(b,c) max + pooled means ----------------
__global__ void __launch_bounds__(256) k_reduce(const float* __restrict__ x){
    int bc = blockIdx.x, t = threadIdx.x;
    int ph = t >> 4, pw = t & 15;
    const float4* q4 = (const float4*)(x + (size_t)bc*HWSZ + ph*8*128 + pw*8);
    float s = 0.f, m = -1e30f;
    #pragma unroll
    for (int r = 0; r < 8; r++){
        float4 a = __ldg(q4 + r*32);
        float4 b = __ldg(q4 + r*32 + 1);
        s += (a.x+a.y)+(a.z+a.w) + (b.x+b.y)+(b.z+b.w);
        m = fmaxf(m, fmaxf(fmaxf(a.x,a.y), fmaxf(a.z,a.w)));
        m = fmaxf(m, fmaxf(fmaxf(b.x,b.y), fmaxf(b.z,b.w)));
    }
    g_xp[bc*PP + t] = s * (1.f/64.f);
    __shared__ float red[256];
    red[t] = m; __syncthreads();
    for (int o = 128; o > 0; o >>= 1){ if (t < o) red[t] = fmaxf(red[t], red[t+o]); __syncthreads(); }
    if (t == 0) g_cmax[bc] = 1.f / (1.f + __expf(-red[0]));
}

__device__ __forceinline__ float blkSum(float v, float* red){
    int t = threadIdx.x; red[t] = v; __syncthreads();
    for (int o = 128; o > 0; o >>= 1){ if (t < o) red[t] += red[t+o]; __syncthreads(); }
    float r = red[0]; __syncthreads(); return r;
}
__device__ __forceinline__ float blkMax(float v, float* red){
    int t = threadIdx.x; red[t] = v; __syncthreads();
    for (int o = 128; o > 0; o >>= 1){ if (t < o) red[t] = fmaxf(red[t], red[t+o]); __syncthreads(); }
    float r = red[0]; __syncthreads(); return r;
}
__device__ __forceinline__ float blkMin(float v, float* red){
    int t = threadIdx.x; red[t] = v; __syncthreads();
    for (int o = 128; o > 0; o >>= 1){ if (t < o) red[t] = fminf(red[t], red[t+o]); __syncthreads(); }
    float r = red[0]; __syncthreads(); return r;
}

// ---------------- kernel 2a: A = I + kc*lap (bf16 split) + spatial stats ----------------
__global__ void __launch_bounds__(256) k_small(){
    __shared__ float red[256];
    __shared__ float cm[CC], rn[CC], inv2s[CC], rowS[CC], colS[CC];
    __shared__ float v[PP];
    int b = blockIdx.x, t = threadIdx.x, lane = t & 31;

    if (t < CC) cm[t] = g_cmax[b*CC + t];
    __syncthreads();
    float cmv = (t < CC) ? cm[t] : 0.f;
    float S1 = blkSum(cmv, red);
    float S2 = blkSum(cmv*cmv, red);
    float nloc = -1e30f;
    if (t < CC){
        float tt = 1.f - cmv;
        float n2 = S2 + 2.f*tt*S1 + 128.f*tt*tt;
        float n  = sqrtf(n2);
        nloc = n;
        rn[t] = 1.f / fmaxf(n, 1e-12f);
    }
    float nmax = blkMax(nloc, red);
    float r = fminf(1.f / fmaxf(nmax, 1e-12f), 1.f);
    if (t < CC){
        float mn = 1e30f;
        for (int j = 0; j < CC; j++) mn = fminf(mn, (cmv + (1.f - cm[j])) * rn[j]);
        float sg = fmaxf(mn, 0.5f);
        inv2s[t] = 1.f / (2.f*sg*sg + 1e-8f);
        rowS[t] = 0.f; colS[t] = 0.f;
    }
    __syncthreads();
    // G pass: each of 128x128 entries once; warp-reduced rowS, spread colS atomics
    #pragma unroll 4
    for (int ii = 0; ii < 64; ii++){
        int idx = ii*256 + t;
        int i = idx >> 7, j = idx & 127;
        float d = fabsf(cm[i] - cm[j]) - r;
        float g = __expf(-d*d*inv2s[i]);
        float g2 = g*g;
        float ws = g2;
        #pragma unroll
        for (int o = 16; o > 0; o >>= 1) ws += __shfl_xor_sync(0xFFFFFFFFu, ws, o);
        if (lane == 0) atomicAdd(&rowS[i], ws);
        atomicAdd(&colS[j], g2);
    }
    __syncthreads();
    const float kc = (float)(128.0/384.0);
    unsigned char* Ah = g_Ahi + (size_t)b*ABYTES;
    unsigned char* Al = g_Alo + (size_t)b*ABYTES;
    for (int idx = t; idx < CC*CC; idx += 256){
        int i = idx >> 7, k = idx & 127;
        float a = 0.5f*(sqrtf(rowS[i]+colS[k]) + sqrtf(rowS[k]+colS[i]));
        float dlt = (i == k) ? 1.f : 0.f;
        float val = kc * cm[i] * (dlt + a) + dlt;           // A = I + kc*lap
        __nv_bfloat16 hi = __float2bfloat16(val);
        __nv_bfloat16 lo = __float2bfloat16(val - __bfloat162float(hi));
        uint32_t o = (uint32_t)(i*ASTRIDE + k)*2u;
        *(__nv_bfloat16*)(Ah + o) = hi;
        *(__nv_bfloat16*)(Al + o) = lo;
    }

    // ---- spatial stats (v, invq, rs only; no softmax passes) ----
    float vv = 0.f;
    for (int c = 0; c < CC; c++) vv += g_xp[((size_t)b*CC + c)*PP + t];
    vv *= (1.f/128.f);
    v[t] = vv;
    __syncthreads();
    float vn2 = blkSum(vv*vv, red);
    float nv = sqrtf(vn2);
    float ns = fabsf(vv)*nv;
    float rns = 1.f / fmaxf(ns, 1e-12f);
    float diag = vv*vv*rns;
    float rs = fminf(blkMin(diag, red), 1.f);
    float mn = 1e30f;
    for (int q = 0; q < PP; q++) mn = fminf(mn, vv*v[q]);
    float sg = fmaxf(mn*rns, 0.5f);
    g_v[b*PP+t] = vv;
    g_invq[b*PP+t] = 1.f/(2.f*sg*sg + 1e-8f);
    if (t == 0) g_rs[b] = rs;
}

// ---------------- kernel 2b: eg = exp(gaussian), coalesced (no max-sub) ----------------
__global__ void __launch_bounds__(256) k_eg(){
    __shared__ float sv[PP];
    int b = blockIdx.x >> 4, pg = blockIdx.x & 15, t = threadIdx.x;
    sv[t] = g_v[b*PP + t];
    __syncthreads();
    float rs = g_rs[b];
    float iqt = __ldg(g_invq + b*PP + t);
    float vq = sv[t];
    #pragma unroll 4
    for (int rr = 0; rr < 16; rr++){
        int p = pg*16 + rr;
        float d = fabsf(sv[p] - vq) - rs;
        float g = __expf(-d*d*iqt);
        g_eg[((size_t)b*PP + p)*PP + t] = __expf(g);
    }
}

// ---------------- kernel 2c: row sums -> rowinv ----------------
__global__ void __launch_bounds__(256) k_rowsum(){
    int b = blockIdx.y, t = threadIdx.x, w = t >> 5, lane = t & 31;
    #pragma unroll
    for (int rr = 0; rr < 4; rr++){
        int p = blockIdx.x*32 + w*4 + rr;
        const float4* row = (const float4*)(g_eg + ((size_t)b*PP + p)*PP);
        float4 a = __ldg(row + lane), c = __ldg(row + lane + 32);
        float s = (a.x+a.y)+(a.z+a.w) + (c.x+c.y)+(c.z+c.w);
        #pragma unroll
        for (int o = 16; o > 0; o >>= 1) s += __shfl_xor_sync(0xFFFFFFFFu, s, o);
        if (lane == 0) g_rowinv[b*PP + p] = 1.f/s;
    }
}

// ---------------- kernel 2d: enh = k_s * (xp*rowinv) @ eg, smem-staged ----------------
__global__ void __launch_bounds__(256) k_enh(){
    __shared__ float sXPN[32*256];   // [c_local][p]
    __shared__ float sEG[32*128];    // [p_local][q_local]
    int b = blockIdx.z, c0 = blockIdx.x*32, q0 = blockIdx.y*128;
    int t = threadIdx.x, wid = t >> 5, qg = t & 31;

    const float* xpb = g_xp + ((size_t)b*CC + c0)*PP;
    const float* riv = g_rowinv + b*PP;
    #pragma unroll 8
    for (int i = 0; i < 32; i++){
        int idx = i*256 + t;
        int c = idx >> 8, p = idx & 255;
        sXPN[idx] = __ldg(xpb + c*PP + p) * __ldg(riv + p);
    }
    float4 a0 = make_float4(0,0,0,0), a1 = a0, a2 = a0, a3 = a0;
    const float* egb = g_eg + (size_t)b*PP*PP + q0;
    const float* xr0 = sXPN + (wid*4+0)*256;
    const float* xr1 = sXPN + (wid*4+1)*256;
    const float* xr2 = sXPN + (wid*4+2)*256;
    const float* xr3 = sXPN + (wid*4+3)*256;
    for (int chunk = 0; chunk < 8; chunk++){
        __syncthreads();
        #pragma unroll
        for (int i = 0; i < 4; i++){
            int idx = i*256 + t;
            int p = idx >> 5, qf = idx & 31;
            ((float4*)sEG)[idx] = __ldg((const float4*)(egb + (size_t)(chunk*32+p)*PP) + qf);
        }
        __syncthreads();
        int pb = chunk*32;
        #pragma unroll 8
        for (int pl = 0; pl < 32; pl++){
            float4 e = ((const float4*)sEG)[pl*32 + qg];
            int p = pb + pl;
            float x0 = xr0[p], x1 = xr1[p], x2 = xr2[p], x3 = xr3[p];
            a0.x += x0*e.x; a0.y += x0*e.y; a0.z += x0*e.z; a0.w += x0*e.w;
            a1.x += x1*e.x; a1.y += x1*e.y; a1.z += x1*e.z; a1.w += x1*e.w;
            a2.x += x2*e.x; a2.y += x2*e.y; a2.z += x2*e.z; a2.w += x2*e.w;
            a3.x += x3*e.x; a3.y += x3*e.y; a3.z += x3*e.z; a3.w += x3*e.w;
        }
    }
    const float ks = (float)(256.0/384.0);
    float* ob = g_enh + ((size_t)b*CC + c0 + wid*4)*PP + q0 + qg*4;
    *(float4*)(ob)         = make_float4(a0.x*ks, a0.y*ks, a0.z*ks, a0.w*ks);
    *(float4*)(ob + PP)    = make_float4(a1.x*ks, a1.y*ks, a1.z*ks, a1.w*ks);
    *(float4*)(ob + 2*PP)  = make_float4(a2.x*ks, a2.y*ks, a2.z*ks, a2.w*ks);
    *(float4*)(ob + 3*PP)  = make_float4(a3.x*ks, a3.y*ks, a3.z*ks, a3.w*ks);
}

// ---------------- kernel 3: mma.sync GEMM + bilinear epilogue ----------------
#define SM_AH  0
#define SM_AL  34816
#define SM_BH  69632
#define SM_BL  104448
#define SM_STG 139264
#define SM_EY  155904
#define SM_WX  164608
#define SM_IX  165120
#define SM_TOTAL 165632

__global__ void __launch_bounds__(256) k_main(const float* __restrict__ x, float* __restrict__ out){
    extern __shared__ __align__(16) unsigned char sm[];
    uint32_t sb = smem_u32(sm);
    int t = threadIdx.x, wid = t >> 5, lane = t & 31;
    int h = blockIdx.x, b = blockIdx.y;

    {
        const float4* ag  = (const float4*)(g_Ahi + (size_t)b*ABYTES);
        const float4* alg = (const float4*)(g_Alo + (size_t)b*ABYTES);
        float4* sa  = (float4*)(sm + SM_AH);
        float4* sal = (float4*)(sm + SM_AL);
        for (int i = t; i < ABYTES/16; i += 256){
            sa[i]  = __ldg(ag + i);
            sal[i] = __ldg(alg + i);
        }
    }
    float sy = h*0.125f - 0.4375f;
    float fl = floorf(sy);
    float fy = sy - fl;
    int iy0 = (int)fl;
    int iy0c = iy0 < 0 ? 0 : iy0;
    int iy1c = iy0+1 > 15 ? 15 : iy0+1;
    if (t < 128){
        float sx = t*0.125f - 0.4375f;
        float f2 = floorf(sx);
        int i0 = (int)f2;
        int i0c = i0 < 0 ? 0 : i0;
        int i1c = i0+1 > 15 ? 15 : i0+1;
        ((float*)(sm + SM_WX))[t] = sx - f2;
        ((int*)(sm + SM_IX))[t] = i0c | (i1c << 8);
        const float* eb = g_enh + ((size_t)b*CC + t)*PP;
        float* ey = (float*)(sm + SM_EY) + t*17;
        #pragma unroll
        for (int px = 0; px < 16; px++){
            float e0 = __ldg(eb + iy0c*16 + px);
            float e1 = __ldg(eb + iy1c*16 + px);
            ey[px] = e0 + fy*(e1 - e0);
        }
    }
    {
        float* stg = (float*)(sm + SM_STG);
        const float* xb = x + (size_t)b*CC*HWSZ + h*128;
        for (int chunk = 0; chunk < 4; chunk++){
            __syncthreads();
            #pragma unroll
            for (int i = 0; i < 4; i++){
                int lin = i*256 + t;
                int c = lin >> 5, wf = lin & 31;
                float4 vv = __ldg((const float4*)(xb + (size_t)(chunk*32 + c)*HWSZ) + wf);
                float* d = stg + c*129 + wf*4;
                d[0] = vv.x; d[1] = vv.y; d[2] = vv.z; d[3] = vv.w;
            }
            __syncthreads();
            int w = t & 127, half = t >> 7;
            int c0 = half*16;
            uint32_t hi[8], lo[8];
            #pragma unroll
            for (int p = 0; p < 8; p++){
                float f0 = stg[(c0 + 2*p)*129 + w];
                float f1 = stg[(c0 + 2*p + 1)*129 + w];
                uint32_t hp;
                asm("cvt.rn.bf16x2.f32 %0, %1, %2;" : "=r"(hp) : "f"(f1), "f"(f0));
                hi[p] = hp;
                float h0 = __uint_as_float(hp << 16);
                float h1 = __uint_as_float(hp & 0xFFFF0000u);
                uint32_t lp;
                float l0 = f0 - h0, l1 = f1 - h1;
                asm("cvt.rn.bf16x2.f32 %0, %1, %2;" : "=r"(lp) : "f"(l1), "f"(l0));
                lo[p] = lp;
            }
            uint32_t o = (uint32_t)(w*ASTRIDE + chunk*32 + c0)*2u;
            *(uint4*)(sm + SM_BH + o)      = make_uint4(hi[0],hi[1],hi[2],hi[3]);
            *(uint4*)(sm + SM_BH + o + 16) = make_uint4(hi[4],hi[5],hi[6],hi[7]);
            *(uint4*)(sm + SM_BL + o)      = make_uint4(lo[0],lo[1],lo[2],lo[3]);
            *(uint4*)(sm + SM_BL + o + 16) = make_uint4(lo[4],lo[5],lo[6],lo[7]);
        }
    }
    __syncthreads();

    int m0 = wid*16;
    int lr = lane & 7;
    uint32_t aA = sb + SM_AH + (uint32_t)(((m0 + lr + (lane & 8))*ASTRIDE + ((lane>>4)<<3))*2);
    uint32_t nB = (uint32_t)(lr + (((lane>>4)&1)<<3));
    uint32_t kB = (uint32_t)(((lane>>3)&1)<<3);
    uint32_t aB = sb + SM_BH + (nB*ASTRIDE + kB)*2u;

    float acc[64];
    #pragma unroll
    for (int i = 0; i < 64; i++) acc[i] = 0.f;

    #pragma unroll
    for (int ks = 0; ks < 8; ks++){
        uint32_t kOff = (uint32_t)(ks*32);
        uint32_t ah[4], al[4];
        LDSM4(ah, aA + kOff);
        LDSM4(al, aA + (SM_AL - SM_AH) + kOff);
        #pragma unroll
        for (int np = 0; np < 8; np++){
            uint32_t bOff = (uint32_t)(np*16*ASTRIDE*2) + kOff;
            uint32_t bh[4], bl[4];
            LDSM4(bh, aB + bOff);
            LDSM4(bl, aB + (SM_BL - SM_BH) + bOff);
            float* d0 = acc + np*8;
            float* d1 = acc + np*8 + 4;
            MMA(d0, ah, bh[0], bh[1]);
            MMA(d1, ah, bh[2], bh[3]);
            MMA(d0, ah, bl[0], bl[1]);
            MMA(d1, ah, bl[2], bl[3]);
            MMA(d0, al, bh[0], bh[1]);
            MMA(d1, al, bh[2], bh[3]);
        }
    }
    {
        int g = lane >> 2, tig = lane & 3;
        int r0 = m0 + g, r1 = r0 + 8;
        const float* ey0 = (const float*)(sm + SM_EY) + r0*17;
        const float* ey1 = (const float*)(sm + SM_EY) + r1*17;
        const float* swx = (const float*)(sm + SM_WX);
        const int*   six = (const int*)(sm + SM_IX);
        float* outB = out + (size_t)b*CC*HWSZ + h*128;
        #pragma unroll
        for (int nt = 0; nt < 16; nt++){
            int n = nt*8 + tig*2;
            const float* d = acc + (nt>>1)*8 + (nt&1)*4;
            int pa = six[n], pb = six[n+1];
            float wa = swx[n], wb = swx[n+1];
            int pa0 = pa & 255, pa1 = (pa >> 8) & 255;
            int pb0 = pb & 255, pb1 = (pb >> 8) & 255;
            float ea = ey0[pa0] + wa*(ey0[pa1] - ey0[pa0]);
            float eb = ey0[pb0] + wb*(ey0[pb1] - ey0[pb0]);
            *(float2*)(outB + (size_t)r0*HWSZ + n) = make_float2(d[0] + ea, d[1] + eb);
            float fa = ey1[pa0] + wa*(ey1[pa1] - ey1[pa0]);
            float fb = ey1[pb0] + wb*(ey1[pb1] - ey1[pb0]);
            *(float2*)(outB + (size_t)r1*HWSZ + n) = make_float2(d[2] + fa, d[3] + fb);
        }
    }
}

extern "C" void kernel_launch(void* const* d_in, const int* in_sizes, int n_in,
                              void* d_out, int out_size){
    const float* x = (const float*)d_in[0];
    float* out = (float*)d_out;
    (void)in_sizes; (void)n_in; (void)out_size;

    k_reduce<<<BB*CC, 256>>>(x);
    k_small<<<BB, 256>>>();
    k_eg<<<BB*16, 256>>>();
    k_rowsum<<<dim3(8, BB), 256>>>();
    k_enh<<<dim3(4, 2, BB), 256>>>();
    cudaFuncSetAttribute(k_main, cudaFuncAttributeMaxDynamicSharedMemorySize, SM_TOTAL);
    k_main<<<dim3(HH, BB), 256, SM_TOTAL>>>(x, out);
}